// round 13
// baseline (speedup 1.0000x reference)
#include <cuda_runtime.h>
#include <cstdint>

// RationalsModel: out[i] = P(x[i]) / (|x[i] * Q(x[i])| + 1)
//   P = sum_{p=0}^{63} coef[p]      * x^p
//   Q = sum_{p=0}^{63} coef[64 + p] * x^p
//
// R13: main kernel is at the validated fma-port floor (R12: 20.35us,
// 1 LDC.64 + 8 FFMA2 per step). Total is staging-bound: strided memcpy2D
// nodes cost ~2us EACH (R12 overhead 4.2us); plain memcpy 0.7-1.2us (R11);
// single kernel ~0.4us (R1/R5/R6). Fix: drop constant memory. A tiny pack
// kernel writes interleaved (coef[p], coef[64+p]) u64 pairs to a __device__
// global; main kernel reads them via __ldg -> LDG.E.64 uniform broadcast
// (L1-hit, same port profile as LDC.64). Graph = 2 kernel nodes, no memcpy.

__device__ __forceinline__ uint64_t pack2(float lo, float hi) {
    uint64_t r;
    asm("mov.b64 %0, {%1, %2};" : "=l"(r) : "f"(lo), "f"(hi));
    return r;
}

__device__ __forceinline__ void unpack2(uint64_t v, float& lo, float& hi) {
    asm("mov.b64 {%0, %1}, %2;" : "=f"(lo), "=f"(hi) : "l"(v));
}

// d = a * b + c  (packed 2x f32)
__device__ __forceinline__ uint64_t fma2(uint64_t a, uint64_t b, uint64_t c) {
    uint64_t d;
    asm("fma.rn.f32x2 %0, %1, %2, %3;" : "=l"(d) : "l"(a), "l"(b), "l"(c));
    return d;
}

// g_pairs[p] = (lo: coef[p] numerator, hi: coef[64+p] denominator)
__device__ __align__(16) uint64_t g_pairs[64];

__global__ void pack_kernel(const float* __restrict__ coef) {
    int p = threadIdx.x;  // 64 threads
    uint32_t lo = __float_as_uint(coef[p]);
    uint32_t hi = __float_as_uint(coef[64 + p]);
    g_pairs[p] = (uint64_t)lo | ((uint64_t)hi << 32);
}

static constexpr int THREADS = 128;
static constexpr int ELEMS_PER_THREAD = 8;                          // 8 (N,D) lanes
static constexpr int ELEMS_PER_BLOCK = THREADS * ELEMS_PER_THREAD;  // 1024
static constexpr int F4_PER_BLOCK = ELEMS_PER_BLOCK / 4;            // 256

__global__ __launch_bounds__(THREADS, 12)
void rational_kernel(const float4* __restrict__ x4,
                     float4* __restrict__ out4)
{
    int tid = threadIdx.x;

    int base = blockIdx.x * F4_PER_BLOCK + tid;
    float4 a = x4[base];
    float4 b = x4[base + THREADS];

    float xs[8] = {a.x, a.y, a.z, a.w, b.x, b.y, b.z, b.w};

    // x2[i] = dup2(x_i): multiplier for the (N,D) packed Horner lane.
    uint64_t x2[8];
#pragma unroll
    for (int j = 0; j < 8; j++) x2[j] = pack2(xs[j], xs[j]);

    // acc[i] = (P_horner_i, Q_horner_i)
    uint64_t acc[8];
    {
        uint64_t c63 = __ldg(&g_pairs[63]);   // (coef[63], coef[127])
#pragma unroll
        for (int j = 0; j < 8; j++) acc[j] = c63;
    }

    // Dual Horner, fully unrolled: per step ONE LDG.64 uniform broadcast
    // (cn,cm) feeding 8 FFMA2 (24 fma-pipe cycles).
#pragma unroll
    for (int p = 62; p >= 0; p--) {
        uint64_t cp = __ldg(&g_pairs[p]);
#pragma unroll
        for (int j = 0; j < 8; j++) {
            acc[j] = fma2(acc[j], x2[j], cp);
        }
    }

    // Epilogue: den = x * Q(x); out = P / (|den| + 1).
    float4 o[2];
    float* of = reinterpret_cast<float*>(o);
#pragma unroll
    for (int j = 0; j < 8; j++) {
        float pn, qd;
        unpack2(acc[j], pn, qd);
        of[j] = __fdividef(pn, fabsf(xs[j] * qd) + 1.0f);
    }

    out4[base] = o[0];
    out4[base + THREADS] = o[1];
}

extern "C" void kernel_launch(void* const* d_in, const int* in_sizes, int n_in,
                              void* d_out, int out_size) {
    const float* x    = (const float*)d_in[0];
    const float* coef = (const float*)d_in[1];
    float* out        = (float*)d_out;

    int N = in_sizes[0];                 // 4194304, divisible by 1024
    int blocks = N / ELEMS_PER_BLOCK;    // 4096

    // 1) Interleave coefficients into u64 pairs in global memory.
    pack_kernel<<<1, 64>>>(coef);

    // 2) Main compute kernel (reads pairs via LDG.64 broadcast).
    rational_kernel<<<blocks, THREADS>>>(
        (const float4*)x, (float4*)out);
}

// round 14
// speedup vs baseline: 1.0908x; 1.0908x over previous
#include <cuda_runtime.h>
#include <cstdint>

// RationalsModel: out[i] = P(x[i]) / (|x[i] * Q(x[i])| + 1)
//   P = sum_{p=0}^{63} coef[p]      * x^p
//   Q = sum_{p=0}^{63} coef[64 + p] * x^p
//
// R14: overhead ledger across R1-R13: every graph node beyond the main
// kernel costs 0.7-2us; single-kernel overhead is ~0.4us. R1-R6's smem
// kernels were CYCLE-optimal (42.1K cyc = rt=3 floor) and lost only to
// DVFS clock (1.73 vs 2.0GHz), correlated with L1 traffic volume.
// This kernel: single node, interleaved (coef[p],coef[64+p]) u64 pairs
// built in-block once, inner loop = 1 LDS.64 broadcast + 8 FFMA2 per step
// (L1 ~10% -> clock should hold ~2GHz). 8 (N,D) lanes per thread.

__device__ __forceinline__ uint64_t pack2(float lo, float hi) {
    uint64_t r;
    asm("mov.b64 %0, {%1, %2};" : "=l"(r) : "f"(lo), "f"(hi));
    return r;
}

__device__ __forceinline__ void unpack2(uint64_t v, float& lo, float& hi) {
    asm("mov.b64 {%0, %1}, %2;" : "=f"(lo), "=f"(hi) : "l"(v));
}

// d = a * b + c  (packed 2x f32)
__device__ __forceinline__ uint64_t fma2(uint64_t a, uint64_t b, uint64_t c) {
    uint64_t d;
    asm("fma.rn.f32x2 %0, %1, %2, %3;" : "=l"(d) : "l"(a), "l"(b), "l"(c));
    return d;
}

static constexpr int THREADS = 128;
static constexpr int ELEMS_PER_THREAD = 8;                          // 8 (N,D) lanes
static constexpr int ELEMS_PER_BLOCK = THREADS * ELEMS_PER_THREAD;  // 1024
static constexpr int F4_PER_BLOCK = ELEMS_PER_BLOCK / 4;            // 256

__global__ __launch_bounds__(THREADS)
void rational_kernel(const float4* __restrict__ x4,
                     const float* __restrict__ coef,
                     float4* __restrict__ out4)
{
    // sP[p] = (lo: coef[p], hi: coef[64+p]) — one LDS.64 broadcast per step.
    __shared__ uint64_t sP[64];

    int tid = threadIdx.x;
    if (tid < 64) {
        uint32_t lo = __float_as_uint(coef[tid]);
        uint32_t hi = __float_as_uint(coef[64 + tid]);
        sP[tid] = (uint64_t)lo | ((uint64_t)hi << 32);
    }
    __syncthreads();

    int base = blockIdx.x * F4_PER_BLOCK + tid;
    float4 a = x4[base];
    float4 b = x4[base + THREADS];

    float xs[8] = {a.x, a.y, a.z, a.w, b.x, b.y, b.z, b.w};

    // x2[i] = dup2(x_i): multiplier for the (N,D) packed Horner lane.
    uint64_t x2[8];
#pragma unroll
    for (int j = 0; j < 8; j++) x2[j] = pack2(xs[j], xs[j]);

    // acc[i] = (P_horner_i, Q_horner_i)
    uint64_t acc[8];
    {
        uint64_t c63 = sP[63];
#pragma unroll
        for (int j = 0; j < 8; j++) acc[j] = c63;
    }

    // Dual Horner, fully unrolled: per step ONE LDS.64 broadcast (cn,cm)
    // feeding 8 FFMA2 (24 fma-pipe cycles).
#pragma unroll
    for (int p = 62; p >= 0; p--) {
        uint64_t cp = sP[p];
#pragma unroll
        for (int j = 0; j < 8; j++) {
            acc[j] = fma2(acc[j], x2[j], cp);
        }
    }

    // Epilogue: den = x * Q(x); out = P / (|den| + 1).
    float4 o[2];
    float* of = reinterpret_cast<float*>(o);
#pragma unroll
    for (int j = 0; j < 8; j++) {
        float pn, qd;
        unpack2(acc[j], pn, qd);
        of[j] = __fdividef(pn, fabsf(xs[j] * qd) + 1.0f);
    }

    out4[base] = o[0];
    out4[base + THREADS] = o[1];
}

extern "C" void kernel_launch(void* const* d_in, const int* in_sizes, int n_in,
                              void* d_out, int out_size) {
    const float* x    = (const float*)d_in[0];
    const float* coef = (const float*)d_in[1];
    float* out        = (float*)d_out;

    int N = in_sizes[0];                 // 4194304, divisible by 1024
    int blocks = N / ELEMS_PER_BLOCK;    // 4096

    rational_kernel<<<blocks, THREADS>>>(
        (const float4*)x, coef, (float4*)out);
}

// round 15
// speedup vs baseline: 1.0923x; 1.0014x over previous
#include <cuda_runtime.h>
#include <cstdint>

// RationalsModel: out[i] = P(x[i]) / (|x[i] * Q(x[i])| + 1)
//   P = sum_{p=0}^{63} coef[p]      * x^p
//   Q = sum_{p=0}^{63} coef[64 + p] * x^p
//
// R15: cycle count is pinned at the FFMA2 rt=3 floor (41.9K cyc). Clock
// ledger: DVFS tracks L1 activity (L1=10% -> 2.06GHz, 24% -> 1.96, 38% ->
// 1.83, 63% -> 1.73). R14 (8 lanes, 1 LDS.64/24 fma-cyc) ran at 1.96GHz.
// This round: 16 (N,D) lanes/thread -> 1 LDS.64 per 48 fma-cycles -> L1
// ~12% -> clock should recover to ~2.05GHz. Low occupancy (regs ~80, ~37%)
// is fine: 16 independent chains per warp saturate the fma port alone.

__device__ __forceinline__ uint64_t pack2(float lo, float hi) {
    uint64_t r;
    asm("mov.b64 %0, {%1, %2};" : "=l"(r) : "f"(lo), "f"(hi));
    return r;
}

__device__ __forceinline__ void unpack2(uint64_t v, float& lo, float& hi) {
    asm("mov.b64 {%0, %1}, %2;" : "=f"(lo), "=f"(hi) : "l"(v));
}

// d = a * b + c  (packed 2x f32)
__device__ __forceinline__ uint64_t fma2(uint64_t a, uint64_t b, uint64_t c) {
    uint64_t d;
    asm("fma.rn.f32x2 %0, %1, %2, %3;" : "=l"(d) : "l"(a), "l"(b), "l"(c));
    return d;
}

static constexpr int THREADS = 128;
static constexpr int LANES = 16;                                    // (N,D) lanes
static constexpr int ELEMS_PER_BLOCK = THREADS * LANES;             // 2048
static constexpr int F4_PER_BLOCK = ELEMS_PER_BLOCK / 4;            // 512

__global__ __launch_bounds__(THREADS)
void rational_kernel(const float4* __restrict__ x4,
                     const float* __restrict__ coef,
                     float4* __restrict__ out4)
{
    // sP[p] = (lo: coef[p], hi: coef[64+p]) — one LDS.64 broadcast per step.
    __shared__ uint64_t sP[64];

    int tid = threadIdx.x;
    if (tid < 64) {
        uint32_t lo = __float_as_uint(coef[tid]);
        uint32_t hi = __float_as_uint(coef[64 + tid]);
        sP[tid] = (uint64_t)lo | ((uint64_t)hi << 32);
    }
    __syncthreads();

    // Four coalesced float4 loads per thread (stride THREADS apart).
    int base = blockIdx.x * F4_PER_BLOCK + tid;
    float4 v0 = x4[base];
    float4 v1 = x4[base + THREADS];
    float4 v2 = x4[base + 2 * THREADS];
    float4 v3 = x4[base + 3 * THREADS];

    // x2[i] = dup2(x_i): multiplier for the (N,D) packed Horner lane.
    uint64_t x2[LANES];
    x2[0]  = pack2(v0.x, v0.x);  x2[1]  = pack2(v0.y, v0.y);
    x2[2]  = pack2(v0.z, v0.z);  x2[3]  = pack2(v0.w, v0.w);
    x2[4]  = pack2(v1.x, v1.x);  x2[5]  = pack2(v1.y, v1.y);
    x2[6]  = pack2(v1.z, v1.z);  x2[7]  = pack2(v1.w, v1.w);
    x2[8]  = pack2(v2.x, v2.x);  x2[9]  = pack2(v2.y, v2.y);
    x2[10] = pack2(v2.z, v2.z);  x2[11] = pack2(v2.w, v2.w);
    x2[12] = pack2(v3.x, v3.x);  x2[13] = pack2(v3.y, v3.y);
    x2[14] = pack2(v3.z, v3.z);  x2[15] = pack2(v3.w, v3.w);

    // acc[i] = (P_horner_i, Q_horner_i)
    uint64_t acc[LANES];
    {
        uint64_t c63 = sP[63];
#pragma unroll
        for (int j = 0; j < LANES; j++) acc[j] = c63;
    }

    // Dual Horner, fully unrolled: per step ONE LDS.64 broadcast (cn,cm)
    // feeding 16 FFMA2 (48 fma-pipe cycles).
#pragma unroll
    for (int p = 62; p >= 0; p--) {
        uint64_t cp = sP[p];
#pragma unroll
        for (int j = 0; j < LANES; j++) {
            acc[j] = fma2(acc[j], x2[j], cp);
        }
    }

    // Epilogue: den = x * Q(x); out = P / (|den| + 1).
    float4 o[4];
    float* of = reinterpret_cast<float*>(o);
#pragma unroll
    for (int j = 0; j < LANES; j++) {
        float pn, qd, xv, xd;
        unpack2(acc[j], pn, qd);
        unpack2(x2[j], xv, xd);
        of[j] = __fdividef(pn, fabsf(xv * qd) + 1.0f);
    }

    out4[base]               = o[0];
    out4[base + THREADS]     = o[1];
    out4[base + 2 * THREADS] = o[2];
    out4[base + 3 * THREADS] = o[3];
}

extern "C" void kernel_launch(void* const* d_in, const int* in_sizes, int n_in,
                              void* d_out, int out_size) {
    const float* x    = (const float*)d_in[0];
    const float* coef = (const float*)d_in[1];
    float* out        = (float*)d_out;

    int N = in_sizes[0];                 // 4194304, divisible by 2048
    int blocks = N / ELEMS_PER_BLOCK;    // 2048

    rational_kernel<<<blocks, THREADS>>>(
        (const float4*)x, coef, (float4*)out);
}